// round 1
// baseline (speedup 1.0000x reference)
#include <cuda_runtime.h>
#include <math.h>

#define DEPTH   6
#define D_MODEL 512
#define N_HEADS 8
#define D_HEAD  64
#define D_FF    2048
#define SEQ_T   2048
#define VOCAB   256
#define BB      2
#define MROWS   (BB * SEQ_T)     /* 4096 */
#define EPS_LN  1e-5f

// ---------------------------------------------------------------------------
// Static device scratch (allocation-free rule)
// ---------------------------------------------------------------------------
__device__ float g_h   [MROWS * D_MODEL];      // residual stream
__device__ float g_ln  [MROWS * D_MODEL];      // layernorm output
__device__ float g_qkv [MROWS * 3 * D_MODEL];  // fused qkv
__device__ float g_attn[MROWS * D_MODEL];      // attention output (pre-proj)
__device__ float g_ff  [MROWS * D_FF];         // fc1/gelu output

// ---------------------------------------------------------------------------
// Embedding: h[b,t,:] = tok_emb[x[b,t],:] + pos_emb[t,:]
// ---------------------------------------------------------------------------
__global__ void embed_kernel(const int* __restrict__ x,
                             const float* __restrict__ tok,
                             const float* __restrict__ pos,
                             float* __restrict__ h) {
    int i = blockIdx.x * blockDim.x + threadIdx.x;
    if (i >= MROWS * D_MODEL) return;
    int d   = i & (D_MODEL - 1);
    int row = i >> 9;              // /512
    int t   = row & (SEQ_T - 1);   // row % 2048
    int tok_id = x[row];
    h[i] = tok[tok_id * D_MODEL + d] + pos[t * D_MODEL + d];
}

// ---------------------------------------------------------------------------
// LayerNorm over D_MODEL=512. One block (256 threads) per row; 2 elems/thread.
// ---------------------------------------------------------------------------
__global__ void ln_kernel(const float* __restrict__ in,
                          const float* __restrict__ w,
                          const float* __restrict__ b,
                          float* __restrict__ out) {
    int row = blockIdx.x;
    int tid = threadIdx.x;
    const float* xr = in + (size_t)row * D_MODEL;

    float v0 = xr[tid];
    float v1 = xr[tid + 256];

    __shared__ float red[256];
    red[tid] = v0 + v1;
    __syncthreads();
    #pragma unroll
    for (int s = 128; s > 0; s >>= 1) {
        if (tid < s) red[tid] += red[tid + s];
        __syncthreads();
    }
    float mu = red[0] * (1.0f / D_MODEL);
    __syncthreads();

    float d0 = v0 - mu, d1 = v1 - mu;
    red[tid] = d0 * d0 + d1 * d1;
    __syncthreads();
    #pragma unroll
    for (int s = 128; s > 0; s >>= 1) {
        if (tid < s) red[tid] += red[tid + s];
        __syncthreads();
    }
    float rstd = rsqrtf(red[0] * (1.0f / D_MODEL) + EPS_LN);

    float* orow = out + (size_t)row * D_MODEL;
    orow[tid]       = d0 * rstd * w[tid]       + b[tid];
    orow[tid + 256] = d1 * rstd * w[tid + 256] + b[tid + 256];
}

// ---------------------------------------------------------------------------
// Tiled SGEMM: Y[M,N] = X[M,K] @ W[N,K]^T  (weights row-major [N,K])
// 64x64 tile, BK=16, 256 threads, 4x4 per thread.
// EPI: 0 = store, 1 = Y += (residual accumulate), 2 = store gelu(val)
// M, N multiples of 64; K multiple of 16 (and of 4 for float4 loads).
// ---------------------------------------------------------------------------
__device__ __forceinline__ float gelu_exact(float x) {
    return 0.5f * x * (1.0f + erff(x * 0.70710678118654752f));
}

template <int EPI>
__global__ void gemm64_kernel(const float* __restrict__ X,
                              const float* __restrict__ W,
                              float* __restrict__ Y,
                              int M, int N, int K) {
    __shared__ float Xs[16][65];
    __shared__ float Ws[16][65];

    int tid = threadIdx.y * 16 + threadIdx.x;  // 0..255
    int tx = threadIdx.x, ty = threadIdx.y;
    int rowBase = blockIdx.y * 64;
    int colBase = blockIdx.x * 64;

    // load indices: each thread loads one float4 per tile per operand
    int lr = tid >> 2;          // 0..63 : tile row
    int lc = (tid & 3) * 4;     // 0,4,8,12 : tile k-offset

    float acc[4][4];
    #pragma unroll
    for (int i = 0; i < 4; i++)
        #pragma unroll
        for (int j = 0; j < 4; j++) acc[i][j] = 0.0f;

    int numKT = K >> 4;
    for (int kt = 0; kt < numKT; kt++) {
        int kBase = kt << 4;
        float4 xa = *(const float4*)&X[(size_t)(rowBase + lr) * K + kBase + lc];
        float4 wa = *(const float4*)&W[(size_t)(colBase + lr) * K + kBase + lc];
        Xs[lc + 0][lr] = xa.x; Xs[lc + 1][lr] = xa.y;
        Xs[lc + 2][lr] = xa.z; Xs[lc + 3][lr] = xa.w;
        Ws[lc + 0][lr] = wa.x; Ws[lc + 1][lr] = wa.y;
        Ws[lc + 2][lr] = wa.z; Ws[lc + 3][lr] = wa.w;
        __syncthreads();

        #pragma unroll
        for (int kk = 0; kk < 16; kk++) {
            float a[4], bv[4];
            #pragma unroll
            for (int i = 0; i < 4; i++) a[i]  = Xs[kk][ty * 4 + i];
            #pragma unroll
            for (int j = 0; j < 4; j++) bv[j] = Ws[kk][tx * 4 + j];
            #pragma unroll
            for (int i = 0; i < 4; i++)
                #pragma unroll
                for (int j = 0; j < 4; j++)
                    acc[i][j] += a[i] * bv[j];
        }
        __syncthreads();
    }

    #pragma unroll
    for (int i = 0; i < 4; i++) {
        int m = rowBase + ty * 4 + i;
        #pragma unroll
        for (int j = 0; j < 4; j++) {
            int n = colBase + tx * 4 + j;
            size_t idx = (size_t)m * N + n;
            if (EPI == 0)      Y[idx] = acc[i][j];
            else if (EPI == 1) Y[idx] += acc[i][j];
            else               Y[idx] = gelu_exact(acc[i][j]);
        }
    }
}

// ---------------------------------------------------------------------------
// Causal attention, one block (256 threads) per (b, h, q).
// qkv layout: [MROWS, 1536]  (q:0..511, k:512..1023, v:1024..1535)
// out layout: [MROWS, 512]   heads interleaved at h*64.
// ---------------------------------------------------------------------------
__global__ void attn_kernel(const float* __restrict__ qkv,
                            float* __restrict__ out) {
    int q = blockIdx.x;
    int h = blockIdx.y;
    int b = blockIdx.z;
    int tid = threadIdx.x;

    __shared__ float qv[D_HEAD];
    __shared__ float sc[SEQ_T];
    __shared__ float red[256];

    const float* rowbase = qkv + (size_t)b * SEQ_T * (3 * D_MODEL);

    if (tid < D_HEAD)
        qv[tid] = rowbase[(size_t)q * (3 * D_MODEL) + h * D_HEAD + tid];
    __syncthreads();

    int L = q + 1;

    // Pass 1: scores + local max
    float lmax = -1e30f;
    for (int k = tid; k < L; k += 256) {
        const float4* kv = (const float4*)(rowbase + (size_t)k * (3 * D_MODEL)
                                           + D_MODEL + h * D_HEAD);
        float s = 0.0f;
        #pragma unroll
        for (int d4 = 0; d4 < D_HEAD / 4; d4++) {
            float4 kk = kv[d4];
            s += qv[d4 * 4 + 0] * kk.x + qv[d4 * 4 + 1] * kk.y
               + qv[d4 * 4 + 2] * kk.z + qv[d4 * 4 + 3] * kk.w;
        }
        s *= 0.125f;  // 1/sqrt(64)
        sc[k] = s;
        lmax = fmaxf(lmax, s);
    }
    red[tid] = lmax;
    __syncthreads();
    #pragma unroll
    for (int s = 128; s > 0; s >>= 1) {
        if (tid < s) red[tid] = fmaxf(red[tid], red[tid + s]);
        __syncthreads();
    }
    float gmax = red[0];
    __syncthreads();

    // Pass 2: exp + sum
    float lsum = 0.0f;
    for (int k = tid; k < L; k += 256) {
        float e = __expf(sc[k] - gmax);
        sc[k] = e;
        lsum += e;
    }
    red[tid] = lsum;
    __syncthreads();
    #pragma unroll
    for (int s = 128; s > 0; s >>= 1) {
        if (tid < s) red[tid] += red[tid + s];
        __syncthreads();
    }
    float inv_sum = 1.0f / red[0];
    __syncthreads();

    // Pass 3: PV.  4 k-groups x 64 d-lanes.
    int grp = tid >> 6;         // 0..3
    int d   = tid & 63;
    const float* vbase = rowbase + 2 * D_MODEL + h * D_HEAD + d;
    float acc = 0.0f;
    for (int k = grp; k < L; k += 4)
        acc += sc[k] * vbase[(size_t)k * (3 * D_MODEL)];

    red[tid] = acc;
    __syncthreads();
    if (tid < 64) {
        float tot = red[tid] + red[tid + 64] + red[tid + 128] + red[tid + 192];
        out[((size_t)b * SEQ_T + q) * D_MODEL + h * D_HEAD + tid] = tot * inv_sum;
    }
}

// ---------------------------------------------------------------------------
// Host launcher
// ---------------------------------------------------------------------------
extern "C" void kernel_launch(void* const* d_in, const int* in_sizes, int n_in,
                              void* d_out, int out_size) {
    const int*   x       = (const int*)  d_in[0];
    const float* tok_emb = (const float*)d_in[1];
    const float* pos_emb = (const float*)d_in[2];
    const float* qkv_w   = (const float*)d_in[3];
    const float* proj_w  = (const float*)d_in[4];
    const float* ln1_w   = (const float*)d_in[5];
    const float* ln1_b   = (const float*)d_in[6];
    const float* ln2_w   = (const float*)d_in[7];
    const float* ln2_b   = (const float*)d_in[8];
    const float* fc1_w   = (const float*)d_in[9];
    const float* fc2_w   = (const float*)d_in[10];
    const float* lnf_w   = (const float*)d_in[11];
    const float* lnf_b   = (const float*)d_in[12];
    const float* head_w  = (const float*)d_in[13];
    float* out = (float*)d_out;

    float *ph, *pln, *pqkv, *pattn, *pff;
    cudaGetSymbolAddress((void**)&ph,    g_h);
    cudaGetSymbolAddress((void**)&pln,   g_ln);
    cudaGetSymbolAddress((void**)&pqkv,  g_qkv);
    cudaGetSymbolAddress((void**)&pattn, g_attn);
    cudaGetSymbolAddress((void**)&pff,   g_ff);

    dim3 gblk(16, 16);

    // Embedding
    embed_kernel<<<(MROWS * D_MODEL + 255) / 256, 256>>>(x, tok_emb, pos_emb, ph);

    for (int l = 0; l < DEPTH; l++) {
        const float* qw  = qkv_w  + (size_t)l * 3 * D_MODEL * D_MODEL;
        const float* pw  = proj_w + (size_t)l * D_MODEL * D_MODEL;
        const float* f1w = fc1_w  + (size_t)l * D_FF * D_MODEL;
        const float* f2w = fc2_w  + (size_t)l * D_MODEL * D_FF;

        // ln1
        ln_kernel<<<MROWS, 256>>>(ph, ln1_w + l * D_MODEL, ln1_b + l * D_MODEL, pln);
        // qkv = ln @ qkv_w^T   [4096 x 1536]
        gemm64_kernel<0><<<dim3(3 * D_MODEL / 64, MROWS / 64), gblk>>>(
            pln, qw, pqkv, MROWS, 3 * D_MODEL, D_MODEL);
        // attention
        attn_kernel<<<dim3(SEQ_T, N_HEADS, BB), 256>>>(pqkv, pattn);
        // h += attn @ proj_w^T
        gemm64_kernel<1><<<dim3(D_MODEL / 64, MROWS / 64), gblk>>>(
            pattn, pw, ph, MROWS, D_MODEL, D_MODEL);
        // ln2
        ln_kernel<<<MROWS, 256>>>(ph, ln2_w + l * D_MODEL, ln2_b + l * D_MODEL, pln);
        // ff = gelu(ln @ fc1_w^T)   [4096 x 2048]
        gemm64_kernel<2><<<dim3(D_FF / 64, MROWS / 64), gblk>>>(
            pln, f1w, pff, MROWS, D_FF, D_MODEL);
        // h += ff @ fc2_w^T
        gemm64_kernel<1><<<dim3(D_MODEL / 64, MROWS / 64), gblk>>>(
            pff, f2w, ph, MROWS, D_MODEL, D_FF);
    }

    // final LN + head
    ln_kernel<<<MROWS, 256>>>(ph, lnf_w, lnf_b, pln);
    gemm64_kernel<0><<<dim3(VOCAB / 64, MROWS / 64), gblk>>>(
        pln, head_w, out, MROWS, VOCAB, D_MODEL);

    (void)in_sizes; (void)n_in; (void)out_size;
}

// round 4
// speedup vs baseline: 2.9797x; 2.9797x over previous
#include <cuda_runtime.h>
#include <math.h>

#define DEPTH   6
#define D_MODEL 512
#define N_HEADS 8
#define D_HEAD  64
#define D_FF    2048
#define SEQ_T   2048
#define VOCAB   256
#define BB      2
#define MROWS   (BB * SEQ_T)     /* 4096 */
#define EPS_LN  1e-5f

// ---------------------------------------------------------------------------
// Static device scratch (allocation-free rule)
// ---------------------------------------------------------------------------
__device__ float g_h   [MROWS * D_MODEL];
__device__ float g_ln  [MROWS * D_MODEL];
__device__ float g_qkv [MROWS * 3 * D_MODEL];
__device__ float g_attn[MROWS * D_MODEL];
__device__ float g_ff  [MROWS * D_FF];

// ---------------------------------------------------------------------------
// Embedding
// ---------------------------------------------------------------------------
__global__ void embed_kernel(const int* __restrict__ x,
                             const float* __restrict__ tok,
                             const float* __restrict__ pos,
                             float* __restrict__ h) {
    int i = blockIdx.x * blockDim.x + threadIdx.x;
    if (i >= MROWS * D_MODEL) return;
    int d   = i & (D_MODEL - 1);
    int row = i >> 9;
    int t   = row & (SEQ_T - 1);
    int tok_id = x[row];
    h[i] = tok[tok_id * D_MODEL + d] + pos[t * D_MODEL + d];
}

// ---------------------------------------------------------------------------
// LayerNorm (one 256-thread block per row of 512)
// ---------------------------------------------------------------------------
__global__ void ln_kernel(const float* __restrict__ in,
                          const float* __restrict__ w,
                          const float* __restrict__ b,
                          float* __restrict__ out) {
    int row = blockIdx.x;
    int tid = threadIdx.x;
    const float* xr = in + (size_t)row * D_MODEL;

    float v0 = xr[tid];
    float v1 = xr[tid + 256];

    __shared__ float red[256];
    red[tid] = v0 + v1;
    __syncthreads();
    #pragma unroll
    for (int s = 128; s > 0; s >>= 1) {
        if (tid < s) red[tid] += red[tid + s];
        __syncthreads();
    }
    float mu = red[0] * (1.0f / D_MODEL);
    __syncthreads();

    float d0 = v0 - mu, d1 = v1 - mu;
    red[tid] = d0 * d0 + d1 * d1;
    __syncthreads();
    #pragma unroll
    for (int s = 128; s > 0; s >>= 1) {
        if (tid < s) red[tid] += red[tid + s];
        __syncthreads();
    }
    float rstd = rsqrtf(red[0] * (1.0f / D_MODEL) + EPS_LN);

    float* orow = out + (size_t)row * D_MODEL;
    orow[tid]       = d0 * rstd * w[tid]       + b[tid];
    orow[tid + 256] = d1 * rstd * w[tid + 256] + b[tid + 256];
}

// ---------------------------------------------------------------------------
// GEMM 128x128x16, double buffered, 256 threads, 8x8 per thread.
// Y[M,N] = X[M,K] @ W[N,K]^T.  EPI: 0 store, 1 Y+=, 2 gelu.
// M,N multiples of 128; K multiple of 16.
// ---------------------------------------------------------------------------
__device__ __forceinline__ float gelu_exact(float x) {
    return 0.5f * x * (1.0f + erff(x * 0.70710678118654752f));
}

template <int EPI>
__global__ __launch_bounds__(256, 2)
void gemm128_kernel(const float* __restrict__ X,
                    const float* __restrict__ W,
                    float* __restrict__ Y,
                    int M, int N, int K) {
    __shared__ float Xs[2][16][128];
    __shared__ float Ws[2][16][128];

    int tid = threadIdx.x;
    int tx = tid & 15;          // n-dim
    int ty = tid >> 4;          // m-dim
    int rowBase = blockIdx.y * 128;
    int colBase = blockIdx.x * 128;

    int lm = tid & 127;         // tile row (0..127)
    int lk = (tid >> 7) * 8;    // 0 or 8

    const float* xptr = X + (size_t)(rowBase + lm) * K + lk;
    const float* wptr = W + (size_t)(colBase + lm) * K + lk;

    float acc[8][8];
    #pragma unroll
    for (int i = 0; i < 8; i++)
        #pragma unroll
        for (int j = 0; j < 8; j++) acc[i][j] = 0.0f;

    // preload tile 0
    float4 px0 = *(const float4*)(xptr);
    float4 px1 = *(const float4*)(xptr + 4);
    float4 pw0 = *(const float4*)(wptr);
    float4 pw1 = *(const float4*)(wptr + 4);
    Xs[0][lk + 0][lm] = px0.x; Xs[0][lk + 1][lm] = px0.y;
    Xs[0][lk + 2][lm] = px0.z; Xs[0][lk + 3][lm] = px0.w;
    Xs[0][lk + 4][lm] = px1.x; Xs[0][lk + 5][lm] = px1.y;
    Xs[0][lk + 6][lm] = px1.z; Xs[0][lk + 7][lm] = px1.w;
    Ws[0][lk + 0][lm] = pw0.x; Ws[0][lk + 1][lm] = pw0.y;
    Ws[0][lk + 2][lm] = pw0.z; Ws[0][lk + 3][lm] = pw0.w;
    Ws[0][lk + 4][lm] = pw1.x; Ws[0][lk + 5][lm] = pw1.y;
    Ws[0][lk + 6][lm] = pw1.z; Ws[0][lk + 7][lm] = pw1.w;
    __syncthreads();

    int nt = K >> 4;
    for (int kt = 0; kt < nt; kt++) {
        int cur = kt & 1;
        bool more = (kt + 1 < nt);
        if (more) {
            int off = (kt + 1) << 4;
            px0 = *(const float4*)(xptr + off);
            px1 = *(const float4*)(xptr + off + 4);
            pw0 = *(const float4*)(wptr + off);
            pw1 = *(const float4*)(wptr + off + 4);
        }

        #pragma unroll
        for (int kk = 0; kk < 16; kk++) {
            float4 xa = *(const float4*)&Xs[cur][kk][ty * 8];
            float4 xb = *(const float4*)&Xs[cur][kk][ty * 8 + 4];
            float4 wa = *(const float4*)&Ws[cur][kk][tx * 8];
            float4 wb = *(const float4*)&Ws[cur][kk][tx * 8 + 4];
            float a[8] = {xa.x, xa.y, xa.z, xa.w, xb.x, xb.y, xb.z, xb.w};
            float bv[8] = {wa.x, wa.y, wa.z, wa.w, wb.x, wb.y, wb.z, wb.w};
            #pragma unroll
            for (int i = 0; i < 8; i++)
                #pragma unroll
                for (int j = 0; j < 8; j++)
                    acc[i][j] += a[i] * bv[j];
        }

        if (more) {
            int alt = cur ^ 1;
            Xs[alt][lk + 0][lm] = px0.x; Xs[alt][lk + 1][lm] = px0.y;
            Xs[alt][lk + 2][lm] = px0.z; Xs[alt][lk + 3][lm] = px0.w;
            Xs[alt][lk + 4][lm] = px1.x; Xs[alt][lk + 5][lm] = px1.y;
            Xs[alt][lk + 6][lm] = px1.z; Xs[alt][lk + 7][lm] = px1.w;
            Ws[alt][lk + 0][lm] = pw0.x; Ws[alt][lk + 1][lm] = pw0.y;
            Ws[alt][lk + 2][lm] = pw0.z; Ws[alt][lk + 3][lm] = pw0.w;
            Ws[alt][lk + 4][lm] = pw1.x; Ws[alt][lk + 5][lm] = pw1.y;
            Ws[alt][lk + 6][lm] = pw1.z; Ws[alt][lk + 7][lm] = pw1.w;
            __syncthreads();
        }
    }

    #pragma unroll
    for (int i = 0; i < 8; i++) {
        int m = rowBase + ty * 8 + i;
        #pragma unroll
        for (int j = 0; j < 8; j++) {
            int n = colBase + tx * 8 + j;
            size_t idx = (size_t)m * N + n;
            if (EPI == 0)      Y[idx] = acc[i][j];
            else if (EPI == 1) Y[idx] += acc[i][j];
            else               Y[idx] = gelu_exact(acc[i][j]);
        }
    }
}

// ---------------------------------------------------------------------------
// GEMM 64x64 (for the head GEMM, N=256)
// ---------------------------------------------------------------------------
template <int EPI>
__global__ void gemm64_kernel(const float* __restrict__ X,
                              const float* __restrict__ W,
                              float* __restrict__ Y,
                              int M, int N, int K) {
    __shared__ float Xs[16][65];
    __shared__ float Ws[16][65];

    int tid = threadIdx.y * 16 + threadIdx.x;
    int tx = threadIdx.x, ty = threadIdx.y;
    int rowBase = blockIdx.y * 64;
    int colBase = blockIdx.x * 64;

    int lr = tid >> 2;
    int lc = (tid & 3) * 4;

    float acc[4][4];
    #pragma unroll
    for (int i = 0; i < 4; i++)
        #pragma unroll
        for (int j = 0; j < 4; j++) acc[i][j] = 0.0f;

    int numKT = K >> 4;
    for (int kt = 0; kt < numKT; kt++) {
        int kBase = kt << 4;
        float4 xa = *(const float4*)&X[(size_t)(rowBase + lr) * K + kBase + lc];
        float4 wa = *(const float4*)&W[(size_t)(colBase + lr) * K + kBase + lc];
        Xs[lc + 0][lr] = xa.x; Xs[lc + 1][lr] = xa.y;
        Xs[lc + 2][lr] = xa.z; Xs[lc + 3][lr] = xa.w;
        Ws[lc + 0][lr] = wa.x; Ws[lc + 1][lr] = wa.y;
        Ws[lc + 2][lr] = wa.z; Ws[lc + 3][lr] = wa.w;
        __syncthreads();

        #pragma unroll
        for (int kk = 0; kk < 16; kk++) {
            float a[4], bv[4];
            #pragma unroll
            for (int i = 0; i < 4; i++) a[i]  = Xs[kk][ty * 4 + i];
            #pragma unroll
            for (int j = 0; j < 4; j++) bv[j] = Ws[kk][tx * 4 + j];
            #pragma unroll
            for (int i = 0; i < 4; i++)
                #pragma unroll
                for (int j = 0; j < 4; j++)
                    acc[i][j] += a[i] * bv[j];
        }
        __syncthreads();
    }

    #pragma unroll
    for (int i = 0; i < 4; i++) {
        int m = rowBase + ty * 4 + i;
        #pragma unroll
        for (int j = 0; j < 4; j++) {
            int n = colBase + tx * 4 + j;
            size_t idx = (size_t)m * N + n;
            if (EPI == 0)      Y[idx] = acc[i][j];
            else if (EPI == 1) Y[idx] += acc[i][j];
            else               Y[idx] = gelu_exact(acc[i][j]);
        }
    }
}

// ---------------------------------------------------------------------------
// Flash attention: one block per (q-tile of 64, head, batch). 256 threads.
// Online softmax, K/V tiles staged through smem once per (q-tile, k-tile).
// qkv layout [MROWS,1536]: q 0..511, k 512..1023, v 1024..1535.
// ---------------------------------------------------------------------------
__global__ __launch_bounds__(256)
void fattn_kernel(const float* __restrict__ qkv,
                  float* __restrict__ out) {
    int qt = blockIdx.x;       // 0..31
    int h  = blockIdx.y;
    int b  = blockIdx.z;
    int tid = threadIdx.x;
    int tx = tid & 15;         // k subtile
    int ty = tid >> 4;         // q subtile

    __shared__ float Qs[64][64];   // [d][q] transposed
    __shared__ float KPs[64][64];  // K transposed [d][k]; reused as P [q][k]
    __shared__ float Vs[64][64];   // [k][d]

    int lq = tid & 63;
    int dg = (tid >> 6) * 16;

    // Load Q tile (transposed)
    {
        const float* qb = qkv + ((size_t)(b * SEQ_T + qt * 64 + lq)) * (3 * D_MODEL)
                        + h * D_HEAD;
        #pragma unroll
        for (int it = 0; it < 4; it++) {
            float4 v = *(const float4*)(qb + dg + it * 4);
            Qs[dg + it * 4 + 0][lq] = v.x;
            Qs[dg + it * 4 + 1][lq] = v.y;
            Qs[dg + it * 4 + 2][lq] = v.z;
            Qs[dg + it * 4 + 3][lq] = v.w;
        }
    }

    float accO[4][4];
    #pragma unroll
    for (int i = 0; i < 4; i++)
        #pragma unroll
        for (int j = 0; j < 4; j++) accO[i][j] = 0.0f;
    float m_i[4] = {-1e30f, -1e30f, -1e30f, -1e30f};
    float l_i[4] = {0.0f, 0.0f, 0.0f, 0.0f};

    __syncthreads();

    for (int kt = 0; kt <= qt; kt++) {
        // Load K tile (transposed) and V tile
        {
            const float* kb = qkv + ((size_t)(b * SEQ_T + kt * 64 + lq)) * (3 * D_MODEL)
                            + D_MODEL + h * D_HEAD;
            #pragma unroll
            for (int it = 0; it < 4; it++) {
                float4 v = *(const float4*)(kb + dg + it * 4);
                KPs[dg + it * 4 + 0][lq] = v.x;
                KPs[dg + it * 4 + 1][lq] = v.y;
                KPs[dg + it * 4 + 2][lq] = v.z;
                KPs[dg + it * 4 + 3][lq] = v.w;
            }
            #pragma unroll
            for (int it = 0; it < 4; it++) {
                int f = it * 256 + tid;
                int kk = f >> 4;
                int d4 = (f & 15) * 4;
                const float* vb = qkv + ((size_t)(b * SEQ_T + kt * 64 + kk)) * (3 * D_MODEL)
                                + 2 * D_MODEL + h * D_HEAD + d4;
                float4 v = *(const float4*)vb;
                *(float4*)&Vs[kk][d4] = v;
            }
        }
        __syncthreads();

        // S = Q K^T (4x4 per thread)
        float s[4][4];
        #pragma unroll
        for (int i = 0; i < 4; i++)
            #pragma unroll
            for (int j = 0; j < 4; j++) s[i][j] = 0.0f;

        #pragma unroll 8
        for (int d = 0; d < 64; d++) {
            float4 qa = *(const float4*)&Qs[d][ty * 4];
            float4 ka = *(const float4*)&KPs[d][tx * 4];
            float a[4] = {qa.x, qa.y, qa.z, qa.w};
            float kv[4] = {ka.x, ka.y, ka.z, ka.w};
            #pragma unroll
            for (int i = 0; i < 4; i++)
                #pragma unroll
                for (int j = 0; j < 4; j++)
                    s[i][j] += a[i] * kv[j];
        }

        // scale + causal mask (diagonal tile only)
        #pragma unroll
        for (int i = 0; i < 4; i++)
            #pragma unroll
            for (int j = 0; j < 4; j++) {
                s[i][j] *= 0.125f;
                if (kt == qt) {
                    int gq = ty * 4 + i;
                    int gk = tx * 4 + j;
                    if (gk > gq) s[i][j] = -1e30f;
                }
            }

        // row max (over j, then across 16 tx lanes)
        float p[4][4];
        #pragma unroll
        for (int i = 0; i < 4; i++) {
            float rmax = fmaxf(fmaxf(s[i][0], s[i][1]), fmaxf(s[i][2], s[i][3]));
            #pragma unroll
            for (int off = 1; off < 16; off <<= 1)
                rmax = fmaxf(rmax, __shfl_xor_sync(0xffffffffu, rmax, off));
            float m_new = fmaxf(m_i[i], rmax);
            float scale = __expf(m_i[i] - m_new);
            float rs = 0.0f;
            #pragma unroll
            for (int j = 0; j < 4; j++) {
                p[i][j] = __expf(s[i][j] - m_new);
                rs += p[i][j];
            }
            #pragma unroll
            for (int off = 1; off < 16; off <<= 1)
                rs += __shfl_xor_sync(0xffffffffu, rs, off);
            l_i[i] = l_i[i] * scale + rs;
            m_i[i] = m_new;
            #pragma unroll
            for (int j = 0; j < 4; j++) accO[i][j] *= scale;
        }

        __syncthreads();  // everyone done reading K before overwriting with P

        // store P as [q][k]
        #pragma unroll
        for (int i = 0; i < 4; i++)
            *(float4*)&KPs[ty * 4 + i][tx * 4] =
                make_float4(p[i][0], p[i][1], p[i][2], p[i][3]);
        __syncthreads();

        // O += P V
        #pragma unroll 4
        for (int k = 0; k < 64; k++) {
            float4 vv = *(const float4*)&Vs[k][tx * 4];
            float v4[4] = {vv.x, vv.y, vv.z, vv.w};
            #pragma unroll
            for (int i = 0; i < 4; i++) {
                float pk = KPs[ty * 4 + i][k];
                #pragma unroll
                for (int j = 0; j < 4; j++)
                    accO[i][j] += pk * v4[j];
            }
        }
        __syncthreads();  // before next tile overwrites KPs/Vs
    }

    // epilogue
    #pragma unroll
    for (int i = 0; i < 4; i++) {
        float inv = 1.0f / l_i[i];
        size_t row = (size_t)(b * SEQ_T + qt * 64 + ty * 4 + i);
        float* orow = out + row * D_MODEL + h * D_HEAD + tx * 4;
        orow[0] = accO[i][0] * inv;
        orow[1] = accO[i][1] * inv;
        orow[2] = accO[i][2] * inv;
        orow[3] = accO[i][3] * inv;
    }
}

// ---------------------------------------------------------------------------
// Host launcher
// ---------------------------------------------------------------------------
extern "C" void kernel_launch(void* const* d_in, const int* in_sizes, int n_in,
                              void* d_out, int out_size) {
    const int*   x       = (const int*)  d_in[0];
    const float* tok_emb = (const float*)d_in[1];
    const float* pos_emb = (const float*)d_in[2];
    const float* qkv_w   = (const float*)d_in[3];
    const float* proj_w  = (const float*)d_in[4];
    const float* ln1_w   = (const float*)d_in[5];
    const float* ln1_b   = (const float*)d_in[6];
    const float* ln2_w   = (const float*)d_in[7];
    const float* ln2_b   = (const float*)d_in[8];
    const float* fc1_w   = (const float*)d_in[9];
    const float* fc2_w   = (const float*)d_in[10];
    const float* lnf_w   = (const float*)d_in[11];
    const float* lnf_b   = (const float*)d_in[12];
    const float* head_w  = (const float*)d_in[13];
    float* out = (float*)d_out;

    float *ph, *pln, *pqkv, *pattn, *pff;
    cudaGetSymbolAddress((void**)&ph,    g_h);
    cudaGetSymbolAddress((void**)&pln,   g_ln);
    cudaGetSymbolAddress((void**)&pqkv,  g_qkv);
    cudaGetSymbolAddress((void**)&pattn, g_attn);
    cudaGetSymbolAddress((void**)&pff,   g_ff);

    embed_kernel<<<(MROWS * D_MODEL + 255) / 256, 256>>>(x, tok_emb, pos_emb, ph);

    for (int l = 0; l < DEPTH; l++) {
        const float* qw  = qkv_w  + (size_t)l * 3 * D_MODEL * D_MODEL;
        const float* pw  = proj_w + (size_t)l * D_MODEL * D_MODEL;
        const float* f1w = fc1_w  + (size_t)l * D_FF * D_MODEL;
        const float* f2w = fc2_w  + (size_t)l * D_MODEL * D_FF;

        ln_kernel<<<MROWS, 256>>>(ph, ln1_w + l * D_MODEL, ln1_b + l * D_MODEL, pln);

        gemm128_kernel<0><<<dim3(3 * D_MODEL / 128, MROWS / 128), 256>>>(
            pln, qw, pqkv, MROWS, 3 * D_MODEL, D_MODEL);

        fattn_kernel<<<dim3(SEQ_T / 64, N_HEADS, BB), 256>>>(pqkv, pattn);

        gemm128_kernel<1><<<dim3(D_MODEL / 128, MROWS / 128), 256>>>(
            pattn, pw, ph, MROWS, D_MODEL, D_MODEL);

        ln_kernel<<<MROWS, 256>>>(ph, ln2_w + l * D_MODEL, ln2_b + l * D_MODEL, pln);

        gemm128_kernel<2><<<dim3(D_FF / 128, MROWS / 128), 256>>>(
            pln, f1w, pff, MROWS, D_FF, D_MODEL);

        gemm128_kernel<1><<<dim3(D_MODEL / 128, MROWS / 128), 256>>>(
            pff, f2w, ph, MROWS, D_MODEL, D_FF);
    }

    ln_kernel<<<MROWS, 256>>>(ph, lnf_w, lnf_b, pln);
    gemm64_kernel<0><<<dim3(VOCAB / 64, MROWS / 64), dim3(16, 16)>>>(
        pln, head_w, out, MROWS, VOCAB, D_MODEL);

    (void)in_sizes; (void)n_in; (void)out_size;
}

// round 5
// speedup vs baseline: 4.1772x; 1.4019x over previous
#include <cuda_runtime.h>
#include <math.h>

#define DEPTH   6
#define D_MODEL 512
#define N_HEADS 8
#define D_HEAD  64
#define D_FF    2048
#define SEQ_T   2048
#define VOCAB   256
#define BB      2
#define MROWS   (BB * SEQ_T)     /* 4096 */
#define EPS_LN  1e-5f

// ---------------------------------------------------------------------------
// Static device scratch
// ---------------------------------------------------------------------------
__device__ float g_h   [MROWS * D_MODEL];
__device__ float g_ln  [MROWS * D_MODEL];
__device__ float g_qkv [MROWS * 3 * D_MODEL];
__device__ float g_attn[MROWS * D_MODEL];
__device__ float g_ff  [MROWS * D_FF];

// ---------------------------------------------------------------------------
// Embedding
// ---------------------------------------------------------------------------
__global__ void embed_kernel(const int* __restrict__ x,
                             const float* __restrict__ tok,
                             const float* __restrict__ pos,
                             float* __restrict__ h) {
    int i = blockIdx.x * blockDim.x + threadIdx.x;
    if (i >= MROWS * D_MODEL) return;
    int d   = i & (D_MODEL - 1);
    int row = i >> 9;
    int t   = row & (SEQ_T - 1);
    int tok_id = x[row];
    h[i] = tok[tok_id * D_MODEL + d] + pos[t * D_MODEL + d];
}

// ---------------------------------------------------------------------------
// LayerNorm
// ---------------------------------------------------------------------------
__global__ void ln_kernel(const float* __restrict__ in,
                          const float* __restrict__ w,
                          const float* __restrict__ b,
                          float* __restrict__ out) {
    int row = blockIdx.x;
    int tid = threadIdx.x;
    const float* xr = in + (size_t)row * D_MODEL;

    float v0 = xr[tid];
    float v1 = xr[tid + 256];

    __shared__ float red[256];
    red[tid] = v0 + v1;
    __syncthreads();
    #pragma unroll
    for (int s = 128; s > 0; s >>= 1) {
        if (tid < s) red[tid] += red[tid + s];
        __syncthreads();
    }
    float mu = red[0] * (1.0f / D_MODEL);
    __syncthreads();

    float d0 = v0 - mu, d1 = v1 - mu;
    red[tid] = d0 * d0 + d1 * d1;
    __syncthreads();
    #pragma unroll
    for (int s = 128; s > 0; s >>= 1) {
        if (tid < s) red[tid] += red[tid + s];
        __syncthreads();
    }
    float rstd = rsqrtf(red[0] * (1.0f / D_MODEL) + EPS_LN);

    float* orow = out + (size_t)row * D_MODEL;
    orow[tid]       = d0 * rstd * w[tid]       + b[tid];
    orow[tid + 256] = d1 * rstd * w[tid + 256] + b[tid + 256];
}

// ---------------------------------------------------------------------------
// tf32 tensor-core GEMM: Y[M,N] = X[M,K] @ W[N,K]^T
// 128x128 block tile, BK=32, 256 threads (8 warps: 4 m x 2 n).
// Warp tile 32x64 = 2 (m16) x 8 (n8) mma.m16n8k8 tiles.
// EPI: 0 store, 1 Y+=, 2 gelu.  M,N mult of 128; K mult of 32.
// ---------------------------------------------------------------------------
__device__ __forceinline__ float gelu_exact(float x) {
    return 0.5f * x * (1.0f + erff(x * 0.70710678118654752f));
}

__device__ __forceinline__ unsigned f2tf(float f) {
    unsigned u;
    asm("cvt.rna.tf32.f32 %0, %1;" : "=r"(u) : "f"(f));
    return u;
}

template <int EPI>
__global__ __launch_bounds__(256, 2)
void gemm_tf32_kernel(const float* __restrict__ X,
                      const float* __restrict__ W,
                      float* __restrict__ Y,
                      int M, int N, int K) {
    __shared__ unsigned Xs[32][132];   // [k][m], tf32 bits
    __shared__ unsigned Ws[32][132];   // [k][n], tf32 bits

    int tid = threadIdx.x;
    int w = tid >> 5, l = tid & 31;
    int wm = w & 3;              // 0..3 (m)
    int wn = w >> 2;             // 0..1 (n)
    int g = l >> 2, t = l & 3;
    int rowBase = blockIdx.y * 128;
    int colBase = blockIdx.x * 128;

    int lm = tid & 127;          // staging row
    int ks = (tid >> 7) * 16;    // staging k-offset (0 or 16)
    const float* xp = X + (size_t)(rowBase + lm) * K + ks;
    const float* wp = W + (size_t)(colBase + lm) * K + ks;

    float acc[2][8][4];
    #pragma unroll
    for (int i = 0; i < 2; i++)
        #pragma unroll
        for (int j = 0; j < 8; j++)
            #pragma unroll
            for (int c = 0; c < 4; c++) acc[i][j][c] = 0.0f;

    int nBK = K >> 5;
    for (int kt = 0; kt < nBK; kt++) {
        int koff = kt << 5;
        #pragma unroll
        for (int c = 0; c < 4; c++) {
            float4 xv = *(const float4*)(xp + koff + c * 4);
            float4 wv = *(const float4*)(wp + koff + c * 4);
            Xs[ks + c * 4 + 0][lm] = f2tf(xv.x);
            Xs[ks + c * 4 + 1][lm] = f2tf(xv.y);
            Xs[ks + c * 4 + 2][lm] = f2tf(xv.z);
            Xs[ks + c * 4 + 3][lm] = f2tf(xv.w);
            Ws[ks + c * 4 + 0][lm] = f2tf(wv.x);
            Ws[ks + c * 4 + 1][lm] = f2tf(wv.y);
            Ws[ks + c * 4 + 2][lm] = f2tf(wv.z);
            Ws[ks + c * 4 + 3][lm] = f2tf(wv.w);
        }
        __syncthreads();

        #pragma unroll
        for (int kb = 0; kb < 32; kb += 8) {
            unsigned a[2][4];
            #pragma unroll
            for (int i = 0; i < 2; i++) {
                int mB = wm * 32 + i * 16;
                a[i][0] = Xs[kb + t]    [mB + g];
                a[i][1] = Xs[kb + t]    [mB + g + 8];
                a[i][2] = Xs[kb + t + 4][mB + g];
                a[i][3] = Xs[kb + t + 4][mB + g + 8];
            }
            #pragma unroll
            for (int j = 0; j < 8; j++) {
                int nB = wn * 64 + j * 8;
                unsigned b0 = Ws[kb + t]    [nB + g];
                unsigned b1 = Ws[kb + t + 4][nB + g];
                #pragma unroll
                for (int i = 0; i < 2; i++) {
                    asm volatile(
                        "mma.sync.aligned.m16n8k8.row.col.f32.tf32.tf32.f32 "
                        "{%0,%1,%2,%3}, {%4,%5,%6,%7}, {%8,%9}, {%0,%1,%2,%3};"
                        : "+f"(acc[i][j][0]), "+f"(acc[i][j][1]),
                          "+f"(acc[i][j][2]), "+f"(acc[i][j][3])
                        : "r"(a[i][0]), "r"(a[i][1]), "r"(a[i][2]), "r"(a[i][3]),
                          "r"(b0), "r"(b1));
                }
            }
        }
        __syncthreads();
    }

    // Epilogue: c0/c1 at (g, 2t/2t+1), c2/c3 at (g+8, ...)
    #pragma unroll
    for (int i = 0; i < 2; i++) {
        int r0 = rowBase + wm * 32 + i * 16 + g;
        #pragma unroll
        for (int j = 0; j < 8; j++) {
            int n = colBase + wn * 64 + j * 8 + 2 * t;
            size_t i0 = (size_t)r0 * N + n;
            size_t i1 = (size_t)(r0 + 8) * N + n;
            if (EPI == 0) {
                *(float2*)&Y[i0] = make_float2(acc[i][j][0], acc[i][j][1]);
                *(float2*)&Y[i1] = make_float2(acc[i][j][2], acc[i][j][3]);
            } else if (EPI == 1) {
                float2 y0 = *(float2*)&Y[i0];
                float2 y1 = *(float2*)&Y[i1];
                y0.x += acc[i][j][0]; y0.y += acc[i][j][1];
                y1.x += acc[i][j][2]; y1.y += acc[i][j][3];
                *(float2*)&Y[i0] = y0;
                *(float2*)&Y[i1] = y1;
            } else {
                *(float2*)&Y[i0] = make_float2(gelu_exact(acc[i][j][0]),
                                               gelu_exact(acc[i][j][1]));
                *(float2*)&Y[i1] = make_float2(gelu_exact(acc[i][j][2]),
                                               gelu_exact(acc[i][j][3]));
            }
        }
    }
}

// ---------------------------------------------------------------------------
// Flash attention (unchanged from R4 — fma/issue bound, 343us/launch)
// ---------------------------------------------------------------------------
__global__ __launch_bounds__(256)
void fattn_kernel(const float* __restrict__ qkv,
                  float* __restrict__ out) {
    int qt = blockIdx.x;
    int h  = blockIdx.y;
    int b  = blockIdx.z;
    int tid = threadIdx.x;
    int tx = tid & 15;
    int ty = tid >> 4;

    __shared__ float Qs[64][64];
    __shared__ float KPs[64][64];
    __shared__ float Vs[64][64];

    int lq = tid & 63;
    int dg = (tid >> 6) * 16;

    {
        const float* qb = qkv + ((size_t)(b * SEQ_T + qt * 64 + lq)) * (3 * D_MODEL)
                        + h * D_HEAD;
        #pragma unroll
        for (int it = 0; it < 4; it++) {
            float4 v = *(const float4*)(qb + dg + it * 4);
            Qs[dg + it * 4 + 0][lq] = v.x;
            Qs[dg + it * 4 + 1][lq] = v.y;
            Qs[dg + it * 4 + 2][lq] = v.z;
            Qs[dg + it * 4 + 3][lq] = v.w;
        }
    }

    float accO[4][4];
    #pragma unroll
    for (int i = 0; i < 4; i++)
        #pragma unroll
        for (int j = 0; j < 4; j++) accO[i][j] = 0.0f;
    float m_i[4] = {-1e30f, -1e30f, -1e30f, -1e30f};
    float l_i[4] = {0.0f, 0.0f, 0.0f, 0.0f};

    __syncthreads();

    for (int kt = 0; kt <= qt; kt++) {
        {
            const float* kb = qkv + ((size_t)(b * SEQ_T + kt * 64 + lq)) * (3 * D_MODEL)
                            + D_MODEL + h * D_HEAD;
            #pragma unroll
            for (int it = 0; it < 4; it++) {
                float4 v = *(const float4*)(kb + dg + it * 4);
                KPs[dg + it * 4 + 0][lq] = v.x;
                KPs[dg + it * 4 + 1][lq] = v.y;
                KPs[dg + it * 4 + 2][lq] = v.z;
                KPs[dg + it * 4 + 3][lq] = v.w;
            }
            #pragma unroll
            for (int it = 0; it < 4; it++) {
                int f = it * 256 + tid;
                int kk = f >> 4;
                int d4 = (f & 15) * 4;
                const float* vb = qkv + ((size_t)(b * SEQ_T + kt * 64 + kk)) * (3 * D_MODEL)
                                + 2 * D_MODEL + h * D_HEAD + d4;
                float4 v = *(const float4*)vb;
                *(float4*)&Vs[kk][d4] = v;
            }
        }
        __syncthreads();

        float s[4][4];
        #pragma unroll
        for (int i = 0; i < 4; i++)
            #pragma unroll
            for (int j = 0; j < 4; j++) s[i][j] = 0.0f;

        #pragma unroll 8
        for (int d = 0; d < 64; d++) {
            float4 qa = *(const float4*)&Qs[d][ty * 4];
            float4 ka = *(const float4*)&KPs[d][tx * 4];
            float a[4] = {qa.x, qa.y, qa.z, qa.w};
            float kv[4] = {ka.x, ka.y, ka.z, ka.w};
            #pragma unroll
            for (int i = 0; i < 4; i++)
                #pragma unroll
                for (int j = 0; j < 4; j++)
                    s[i][j] += a[i] * kv[j];
        }

        #pragma unroll
        for (int i = 0; i < 4; i++)
            #pragma unroll
            for (int j = 0; j < 4; j++) {
                s[i][j] *= 0.125f;
                if (kt == qt) {
                    int gq = ty * 4 + i;
                    int gk = tx * 4 + j;
                    if (gk > gq) s[i][j] = -1e30f;
                }
            }

        float p[4][4];
        #pragma unroll
        for (int i = 0; i < 4; i++) {
            float rmax = fmaxf(fmaxf(s[i][0], s[i][1]), fmaxf(s[i][2], s[i][3]));
            #pragma unroll
            for (int off = 1; off < 16; off <<= 1)
                rmax = fmaxf(rmax, __shfl_xor_sync(0xffffffffu, rmax, off));
            float m_new = fmaxf(m_i[i], rmax);
            float scale = __expf(m_i[i] - m_new);
            float rs = 0.0f;
            #pragma unroll
            for (int j = 0; j < 4; j++) {
                p[i][j] = __expf(s[i][j] - m_new);
                rs += p[i][j];
            }
            #pragma unroll
            for (int off = 1; off < 16; off <<= 1)
                rs += __shfl_xor_sync(0xffffffffu, rs, off);
            l_i[i] = l_i[i] * scale + rs;
            m_i[i] = m_new;
            #pragma unroll
            for (int j = 0; j < 4; j++) accO[i][j] *= scale;
        }

        __syncthreads();

        #pragma unroll
        for (int i = 0; i < 4; i++)
            *(float4*)&KPs[ty * 4 + i][tx * 4] =
                make_float4(p[i][0], p[i][1], p[i][2], p[i][3]);
        __syncthreads();

        #pragma unroll 4
        for (int k = 0; k < 64; k++) {
            float4 vv = *(const float4*)&Vs[k][tx * 4];
            float v4[4] = {vv.x, vv.y, vv.z, vv.w};
            #pragma unroll
            for (int i = 0; i < 4; i++) {
                float pk = KPs[ty * 4 + i][k];
                #pragma unroll
                for (int j = 0; j < 4; j++)
                    accO[i][j] += pk * v4[j];
            }
        }
        __syncthreads();
    }

    #pragma unroll
    for (int i = 0; i < 4; i++) {
        float inv = 1.0f / l_i[i];
        size_t row = (size_t)(b * SEQ_T + qt * 64 + ty * 4 + i);
        float* orow = out + row * D_MODEL + h * D_HEAD + tx * 4;
        orow[0] = accO[i][0] * inv;
        orow[1] = accO[i][1] * inv;
        orow[2] = accO[i][2] * inv;
        orow[3] = accO[i][3] * inv;
    }
}

// ---------------------------------------------------------------------------
// Host launcher
// ---------------------------------------------------------------------------
extern "C" void kernel_launch(void* const* d_in, const int* in_sizes, int n_in,
                              void* d_out, int out_size) {
    const int*   x       = (const int*)  d_in[0];
    const float* tok_emb = (const float*)d_in[1];
    const float* pos_emb = (const float*)d_in[2];
    const float* qkv_w   = (const float*)d_in[3];
    const float* proj_w  = (const float*)d_in[4];
    const float* ln1_w   = (const float*)d_in[5];
    const float* ln1_b   = (const float*)d_in[6];
    const float* ln2_w   = (const float*)d_in[7];
    const float* ln2_b   = (const float*)d_in[8];
    const float* fc1_w   = (const float*)d_in[9];
    const float* fc2_w   = (const float*)d_in[10];
    const float* lnf_w   = (const float*)d_in[11];
    const float* lnf_b   = (const float*)d_in[12];
    const float* head_w  = (const float*)d_in[13];
    float* out = (float*)d_out;

    float *ph, *pln, *pqkv, *pattn, *pff;
    cudaGetSymbolAddress((void**)&ph,    g_h);
    cudaGetSymbolAddress((void**)&pln,   g_ln);
    cudaGetSymbolAddress((void**)&pqkv,  g_qkv);
    cudaGetSymbolAddress((void**)&pattn, g_attn);
    cudaGetSymbolAddress((void**)&pff,   g_ff);

    embed_kernel<<<(MROWS * D_MODEL + 255) / 256, 256>>>(x, tok_emb, pos_emb, ph);

    for (int l = 0; l < DEPTH; l++) {
        const float* qw  = qkv_w  + (size_t)l * 3 * D_MODEL * D_MODEL;
        const float* pw  = proj_w + (size_t)l * D_MODEL * D_MODEL;
        const float* f1w = fc1_w  + (size_t)l * D_FF * D_MODEL;
        const float* f2w = fc2_w  + (size_t)l * D_MODEL * D_FF;

        ln_kernel<<<MROWS, 256>>>(ph, ln1_w + l * D_MODEL, ln1_b + l * D_MODEL, pln);

        gemm_tf32_kernel<0><<<dim3(3 * D_MODEL / 128, MROWS / 128), 256>>>(
            pln, qw, pqkv, MROWS, 3 * D_MODEL, D_MODEL);

        fattn_kernel<<<dim3(SEQ_T / 64, N_HEADS, BB), 256>>>(pqkv, pattn);

        gemm_tf32_kernel<1><<<dim3(D_MODEL / 128, MROWS / 128), 256>>>(
            pattn, pw, ph, MROWS, D_MODEL, D_MODEL);

        ln_kernel<<<MROWS, 256>>>(ph, ln2_w + l * D_MODEL, ln2_b + l * D_MODEL, pln);

        gemm_tf32_kernel<2><<<dim3(D_FF / 128, MROWS / 128), 256>>>(
            pln, f1w, pff, MROWS, D_FF, D_MODEL);

        gemm_tf32_kernel<1><<<dim3(D_MODEL / 128, MROWS / 128), 256>>>(
            pff, f2w, ph, MROWS, D_MODEL, D_FF);
    }

    ln_kernel<<<MROWS, 256>>>(ph, lnf_w, lnf_b, pln);
    gemm_tf32_kernel<0><<<dim3(VOCAB / 128, MROWS / 128), 256>>>(
        pln, head_w, out, MROWS, VOCAB, D_MODEL);

    (void)in_sizes; (void)n_in; (void)out_size;
}